// round 16
// baseline (speedup 1.0000x reference)
#include <cuda_runtime.h>
#include <cstdint>

// Fixed problem shapes
#define BB 4
#define HH 224
#define WW 224
#define CC 16
#define FF 32
#define HO 220
#define WO 220
#define WG (WW / 4)   // 56 u32 words per planar row

#define MAGIC_I 0x4B400000
#define MAGIC_F 12582912.0f
#define NMAGIC2 0xCB400000CB400000ULL   // f32x2 pair (-12582912, -12582912)

typedef unsigned long long u64;

// Channel-planar u8 scratch: P[b][c][h][w] (3.2 MB static device global)
__device__ unsigned char g_planar[BB * CC * HH * WW];

__device__ __forceinline__ int dp4a_us(unsigned a, unsigned b, int c) {
    int d;
    asm("dp4a.u32.s32 %0, %1, %2, %3;" : "=r"(d) : "r"(a), "r"(b), "r"(c));
    return d;
}

// f32x2 packed ops (sm_103a; FFMA2 reachable only via PTX)
__device__ __forceinline__ u64 pack2(float lo, float hi) {
    u64 r;
    asm("mov.b64 %0, {%1, %2};" : "=l"(r) : "f"(lo), "f"(hi));
    return r;
}
__device__ __forceinline__ u64 fma2(u64 a, u64 b, u64 c) {
    u64 d;
    asm("fma.rn.f32x2 %0, %1, %2, %3;" : "=l"(d) : "l"(a), "l"(b), "l"(c));
    return d;
}
__device__ __forceinline__ u64 add2(u64 a, u64 b) {
    u64 d;
    asm("add.rn.f32x2 %0, %1, %2;" : "=l"(d) : "l"(a), "l"(b));
    return d;
}

// Magic-offset word for an integer-valued float in [0,255]: low byte == value.
__device__ __forceinline__ unsigned f2b(float f) {
    return __float_as_uint(f + 8388608.0f);
}
// Unpack byte t (0..3) of word into an exact float (PRMT + FSUB).
__device__ __forceinline__ float byte2f(unsigned word, int t) {
    unsigned r = __byte_perm(word, 0x4B400000u, 0x7650u + (unsigned)t);
    return __uint_as_float(r) - MAGIC_F;
}

// -------------------------------------------------------------------------
// Prepass: NHWC fp32 -> planar u8. 2 image rows per block, FADD-magic
// conversion (no F2I), aligned u32 phase-2 reads.
// -------------------------------------------------------------------------
__global__ __launch_bounds__(512) void prepass_kernel(const float* __restrict__ in) {
    __shared__ unsigned char sm[2][CC][WW + 4];
    int bh2 = blockIdx.x;                 // 0 .. BB*HH/2-1
    int b = bh2 / (HH / 2), hr = bh2 % (HH / 2);
    int h0 = hr * 2;
    const float* row = in + (size_t)(b * HH + h0) * WW * CC;

    for (int l = threadIdx.x; l < 2 * WW * CC; l += 512) {
        int r = l / (WW * CC), k = l % (WW * CC);
        int w = k >> 4, c = k & 15;       // contiguous float reads
        sm[r][c][w] = (unsigned char)f2b(row[l]);
    }
    __syncthreads();

    unsigned* dst = (unsigned*)g_planar;
    for (int l = threadIdx.x; l < 2 * CC * WG; l += 512) {
        int r = l / (CC * WG), k = l % (CC * WG);
        int c = k / WG, g = k % WG;
        unsigned v = *(const unsigned*)&sm[r][c][4 * g];   // aligned: 228c+4g
        dst[((b * CC + c) * HH + h0 + r) * WG + g] = v;
    }
}

// One float4 output group: rows 0-3 via 20 dp4a (IDP pipe), row 4 via 10
// packed FFMA2 on pre-paired floats (FMA pipe, 2 MACs/slot).
__device__ __forceinline__ void conv_group4(
    uint4 va, uint4 vb, const u64* Xp,
    uint4 w0, unsigned kv4,
    u64 wp0, u64 wp1, u64 wp2, u64 wp3, u64 wp4, float* pb)
{
    // dp4a part: rows ho..ho+3 (accumulator starts at the i2f magic word)
    int a0 = dp4a_us(va.x, w0.x, MAGIC_I);
    a0 = dp4a_us(va.y, w0.y, a0);
    a0 = dp4a_us(va.z, w0.z, a0);
    a0 = dp4a_us(va.w, w0.w, a0);
    a0 = dp4a_us(vb.x, kv4, a0);

    int a1 = dp4a_us(va.y, w0.x, MAGIC_I);
    a1 = dp4a_us(va.z, w0.y, a1);
    a1 = dp4a_us(va.w, w0.z, a1);
    a1 = dp4a_us(vb.x, w0.w, a1);
    a1 = dp4a_us(vb.y, kv4, a1);

    int a2 = dp4a_us(va.z, w0.x, MAGIC_I);
    a2 = dp4a_us(va.w, w0.y, a2);
    a2 = dp4a_us(vb.x, w0.z, a2);
    a2 = dp4a_us(vb.y, w0.w, a2);
    a2 = dp4a_us(vb.z, kv4, a2);

    int a3 = dp4a_us(va.w, w0.x, MAGIC_I);
    a3 = dp4a_us(vb.x, w0.y, a3);
    a3 = dp4a_us(vb.y, w0.z, a3);
    a3 = dp4a_us(vb.z, w0.w, a3);
    a3 = dp4a_us(vb.w, kv4, a3);

    // f32x2 part: row ho+4. Pair (f0,f1) uses Xp[j], pair (f2,f3) Xp[j+2].
    // All intermediates exact integers offset by 12582912 (< 2^24).
    u64 f01 = pack2(__int_as_float(a0), __int_as_float(a1));
    u64 f23 = pack2(__int_as_float(a2), __int_as_float(a3));

    f01 = fma2(Xp[0], wp0, f01);
    f23 = fma2(Xp[2], wp0, f23);
    f01 = fma2(Xp[1], wp1, f01);
    f23 = fma2(Xp[3], wp1, f23);
    f01 = fma2(Xp[2], wp2, f01);
    f23 = fma2(Xp[4], wp2, f23);
    f01 = fma2(Xp[3], wp3, f01);
    f23 = fma2(Xp[5], wp3, f23);
    f01 = fma2(Xp[4], wp4, f01);
    f23 = fma2(Xp[6], wp4, f23);

    f01 = add2(f01, NMAGIC2);
    f23 = add2(f23, NMAGIC2);

    __stcs((double2*)pb, make_double2(__longlong_as_double((long long)f01),
                                      __longlong_as_double((long long)f23)));
}

// Process one 32-group half. ALL=true: every lane active (no predication).
template<bool ALL>
__device__ __forceinline__ void process_half(
    int g, const unsigned* Vrow, const unsigned* R4, float* rowbase,
    const uint4* W0sm, const ulonglong2* WDab, const ulonglong2* WDcd,
    const ulonglong2* Wmix, int pbase)
{
    bool act = ALL ? true : (g < 55);    // 55 float4 groups cover WO=220
    uint4 va, vb;
    u64 Xp[7];                           // row ho+4 float pairs (X[j],X[j+1])
    if (act) {
        va = *(const uint4*)(Vrow + 4 * g);       // cols 4g..4g+3
        vb = *(const uint4*)(Vrow + 4 * g + 4);   // cols 4g+4..4g+7
        unsigned ra = R4[g];
        unsigned rb = R4[g + 1];
        float X4[8];
#pragma unroll
        for (int s = 0; s < 4; s++) {
            X4[s] = byte2f(ra, s);
            X4[4 + s] = byte2f(rb, s);
        }
#pragma unroll
        for (int j = 0; j < 7; j++)
            Xp[j] = pack2(X4[j], X4[j + 1]);
    }
    float* pb = rowbase + 4 * g;

#pragma unroll 2
    for (int ff = 0; ff < FF; ff += 2) {
        // Load BOTH iterations' weights first (broadcast LDS.128 x4 each),
        // then run independent dp4a/FFMA2 chains -> LDS latency covered.
        uint4 w0a = W0sm[pbase + ff];
        ulonglong2 dab_a = WDab[pbase + ff];
        ulonglong2 dcd_a = WDcd[pbase + ff];
        ulonglong2 mx_a = Wmix[pbase + ff];
        uint4 w0b = W0sm[pbase + ff + 1];
        ulonglong2 dab_b = WDab[pbase + ff + 1];
        ulonglong2 dcd_b = WDcd[pbase + ff + 1];
        ulonglong2 mx_b = Wmix[pbase + ff + 1];

        if (act) {
            conv_group4(va, vb, Xp, w0a, (unsigned)mx_a.x,
                        dab_a.x, dab_a.y, dcd_a.x, dcd_a.y, mx_a.y,
                        pb + ff * WO);
            conv_group4(va, vb, Xp, w0b, (unsigned)mx_b.x,
                        dab_b.x, dab_b.y, dcd_b.x, dcd_b.y, mx_b.y,
                        pb + (ff + 1) * WO);
        }
    }
}

// -------------------------------------------------------------------------
// Main conv kernel.
// grid = B*HO*2 (1760). block = 256 threads = 8 warps = 8 channels.
// lane = wo-group; pass0 all 32 lanes, pass1 lanes 0-22 (55 groups total).
// Weight tables per (c,f): W0 = packed rows0-3 cols0-3,
// WDab/WDcd = row-4 weights pre-DUPLICATED f32x2 pairs (wp0..wp3),
// Wmix = (kv4 in low32, wp4) -- one LDS.128 serves both.
// __launch_bounds__(256,5): regs <= 51 -> 5 resident blocks (occ 62.5%).
// -------------------------------------------------------------------------
__global__ __launch_bounds__(256, 5) void conv_main_kernel(
    const float* __restrict__ kern, float* __restrict__ out)
{
    __shared__ __align__(16) unsigned Vsm[8][WW];     // 7168 B
    __shared__ unsigned R4sm[8][WG];                  // 1792 B
    __shared__ __align__(16) uint4 W0sm[256];         // 4096 B
    __shared__ __align__(16) ulonglong2 WDab[256];    // 4096 B (wp0, wp1)
    __shared__ __align__(16) ulonglong2 WDcd[256];    // 4096 B (wp2, wp3)
    __shared__ __align__(16) ulonglong2 Wmix[256];    // 4096 B (kv4, wp4)  25344 total

    int bid = blockIdx.x;
    int chalf = bid & 1;
    int t = bid >> 1;
    int ho = t % HO;
    int b = t / HO;
    int tid = threadIdx.x;
    int wid = tid >> 5;              // local channel 0..7
    int lane = tid & 31;
    int cg = chalf * 8 + wid;        // global channel

    // ---- Pack weights: thread = (local c, f) = (wid, lane) ----
    {
        int kk[25];
#pragma unroll
        for (int tt = 0; tt < 25; tt++)
            kk[tt] = (int)kern[tt * (CC * FF) + cg * FF + lane];
        unsigned Kv[5];
#pragma unroll
        for (int j = 0; j < 5; j++)
            Kv[j] = ((unsigned)(kk[j] & 0xFF))
                  | ((unsigned)(kk[5 + j] & 0xFF) << 8)
                  | ((unsigned)(kk[10 + j] & 0xFF) << 16)
                  | ((unsigned)(kk[15 + j] & 0xFF) << 24);
        W0sm[tid] = make_uint4(Kv[0], Kv[1], Kv[2], Kv[3]);
        unsigned d0 = __float_as_uint((float)kk[20]);
        unsigned d1 = __float_as_uint((float)kk[21]);
        unsigned d2 = __float_as_uint((float)kk[22]);
        unsigned d3 = __float_as_uint((float)kk[23]);
        unsigned d4 = __float_as_uint((float)kk[24]);
        WDab[tid] = make_ulonglong2(d0 | ((u64)d0 << 32), d1 | ((u64)d1 << 32));
        WDcd[tid] = make_ulonglong2(d2 | ((u64)d2 << 32), d3 | ((u64)d3 << 32));
        Wmix[tid] = make_ulonglong2((u64)Kv[4], d4 | ((u64)d4 << 32));
    }

    // ---- Stage 5 planar rows for our 8 channels; 8-PRMT vertical transpose ----
    const unsigned* P = (const unsigned*)g_planar;
    for (int l = tid; l < 8 * WG; l += 256) {
        int cc = l / WG, g = l % WG;
        const unsigned* base =
            P + ((size_t)(b * CC + chalf * 8 + cc) * HH + ho) * WG + g;
        unsigned r0 = base[0 * WG];
        unsigned r1 = base[1 * WG];
        unsigned r2 = base[2 * WG];
        unsigned r3 = base[3 * WG];
        unsigned r4 = base[4 * WG];
        unsigned t0 = __byte_perm(r0, r1, 0x5140);
        unsigned t1 = __byte_perm(r0, r1, 0x7362);
        unsigned t2 = __byte_perm(r2, r3, 0x5140);
        unsigned t3 = __byte_perm(r2, r3, 0x7362);
        uint4 v;
        v.x = __byte_perm(t0, t2, 0x5410);
        v.y = __byte_perm(t0, t2, 0x7632);
        v.z = __byte_perm(t1, t3, 0x5410);
        v.w = __byte_perm(t1, t3, 0x7632);
        *(uint4*)&Vsm[cc][4 * g] = v;
        R4sm[cc][g] = r4;
    }
    __syncthreads();

    const unsigned* Vrow = &Vsm[wid][0];
    const unsigned* R4 = &R4sm[wid][0];
    float* rowbase = out + ((size_t)(b * HO + ho) * CC + cg) * FF * WO;
    const int pbase = wid * 32;

    // Pass 0: groups 0..31 -- every lane active, no predication.
    process_half<true>(lane, Vrow, R4, rowbase, W0sm, WDab, WDcd, Wmix, pbase);
    // Pass 1: groups 32..54 -- lanes 0..22 active.
    process_half<false>(lane + 32, Vrow, R4, rowbase, W0sm, WDab, WDcd, Wmix, pbase);
}

// -------------------------------------------------------------------------
// kernel_launch: prepass + main conv. Graph-capturable: 2 launches, no sync,
// no allocation (scratch is a static __device__ array).
// -------------------------------------------------------------------------
extern "C" void kernel_launch(void* const* d_in, const int* in_sizes, int n_in,
                              void* d_out, int out_size) {
    const float* inputs = (const float*)d_in[0];  // [4,224,224,16] f32
    const float* kernel = (const float*)d_in[1];  // [5,5,16,32]    f32
    float* out = (float*)d_out;                   // [4,220,16,32,220] f32

    prepass_kernel<<<BB * HH / 2, 512>>>(inputs);
    conv_main_kernel<<<BB * HO * 2, 256>>>(kernel, out);
}

// round 17
// speedup vs baseline: 1.6231x; 1.6231x over previous
#include <cuda_runtime.h>
#include <cstdint>

// Fixed problem shapes
#define BB 4
#define HH 224
#define WW 224
#define CC 16
#define FF 32
#define HO 220
#define WO 220
#define WG (WW / 4)   // 56 u32 words per planar row

#define MAGIC_I 0x4B400000
#define MAGIC_F 12582912.0f
#define NMAGIC2 0xCB400000CB400000ULL   // f32x2 pair (-12582912, -12582912)

typedef unsigned long long u64;

// Channel-planar u8 scratch: P[b][c][h][w] (3.2 MB static device global)
__device__ unsigned char g_planar[BB * CC * HH * WW];

__device__ __forceinline__ int dp4a_us(unsigned a, unsigned b, int c) {
    int d;
    asm("dp4a.u32.s32 %0, %1, %2, %3;" : "=r"(d) : "r"(a), "r"(b), "r"(c));
    return d;
}

// f32x2 packed ops (sm_103a; FFMA2 reachable only via PTX)
__device__ __forceinline__ u64 pack2(float lo, float hi) {
    u64 r;
    asm("mov.b64 %0, {%1, %2};" : "=l"(r) : "f"(lo), "f"(hi));
    return r;
}
__device__ __forceinline__ u64 fma2(u64 a, u64 b, u64 c) {
    u64 d;
    asm("fma.rn.f32x2 %0, %1, %2, %3;" : "=l"(d) : "l"(a), "l"(b), "l"(c));
    return d;
}
__device__ __forceinline__ u64 add2(u64 a, u64 b) {
    u64 d;
    asm("add.rn.f32x2 %0, %1, %2;" : "=l"(d) : "l"(a), "l"(b));
    return d;
}

// Magic-offset word for an integer-valued float in [0,255]: low byte == value.
__device__ __forceinline__ unsigned f2b(float f) {
    return __float_as_uint(f + 8388608.0f);
}
// Unpack byte t (0..3) of word into an exact float (PRMT + FSUB).
__device__ __forceinline__ float byte2f(unsigned word, int t) {
    unsigned r = __byte_perm(word, 0x4B400000u, 0x7650u + (unsigned)t);
    return __uint_as_float(r) - MAGIC_F;
}

// -------------------------------------------------------------------------
// Prepass: NHWC fp32 -> planar u8. 2 image rows per block; phase-1 reads are
// float4 (4 channels of one pixel per thread -> LDG.128); FADD-magic
// conversion (no F2I pipe); aligned u32 phase-2 reads.
// -------------------------------------------------------------------------
__global__ __launch_bounds__(512) void prepass_kernel(const float* __restrict__ in) {
    __shared__ unsigned char sm[2][CC][WW + 4];
    int bh2 = blockIdx.x;                 // 0 .. BB*HH/2-1
    int b = bh2 / (HH / 2), hr = bh2 % (HH / 2);
    int h0 = hr * 2;
    const float* row = in + (size_t)(b * HH + h0) * WW * CC;

    // 2 rows * 224 px * 4 quads = 1792 float4 loads
    for (int l = threadIdx.x; l < 2 * WW * 4; l += 512) {
        int r = l / (WW * 4), k = l % (WW * 4);
        int w = k >> 2, cq = k & 3;       // quad cq covers channels 4cq..4cq+3
        float4 v = *(const float4*)(row + (size_t)r * WW * CC + w * CC + cq * 4);
        sm[r][cq * 4 + 0][w] = (unsigned char)f2b(v.x);
        sm[r][cq * 4 + 1][w] = (unsigned char)f2b(v.y);
        sm[r][cq * 4 + 2][w] = (unsigned char)f2b(v.z);
        sm[r][cq * 4 + 3][w] = (unsigned char)f2b(v.w);
    }
    __syncthreads();

    unsigned* dst = (unsigned*)g_planar;
    for (int l = threadIdx.x; l < 2 * CC * WG; l += 512) {
        int r = l / (CC * WG), k = l % (CC * WG);
        int c = k / WG, g = k % WG;
        unsigned v = *(const unsigned*)&sm[r][c][4 * g];   // aligned: 228c+4g
        dst[((b * CC + c) * HH + h0 + r) * WG + g] = v;
    }
}

// One float4 output group: rows 0-3 via 20 dp4a (IDP pipe), row 4 via 10
// packed FFMA2 on pre-paired floats (FMA pipe, 2 MACs/slot).
__device__ __forceinline__ void conv_group4(
    uint4 va, uint4 vb, const u64* Xp,
    uint4 w0, unsigned kv4,
    u64 wp0, u64 wp1, u64 wp2, u64 wp3, u64 wp4, float* pb)
{
    // dp4a part: rows ho..ho+3 (accumulator starts at the i2f magic word)
    int a0 = dp4a_us(va.x, w0.x, MAGIC_I);
    a0 = dp4a_us(va.y, w0.y, a0);
    a0 = dp4a_us(va.z, w0.z, a0);
    a0 = dp4a_us(va.w, w0.w, a0);
    a0 = dp4a_us(vb.x, kv4, a0);

    int a1 = dp4a_us(va.y, w0.x, MAGIC_I);
    a1 = dp4a_us(va.z, w0.y, a1);
    a1 = dp4a_us(va.w, w0.z, a1);
    a1 = dp4a_us(vb.x, w0.w, a1);
    a1 = dp4a_us(vb.y, kv4, a1);

    int a2 = dp4a_us(va.z, w0.x, MAGIC_I);
    a2 = dp4a_us(va.w, w0.y, a2);
    a2 = dp4a_us(vb.x, w0.z, a2);
    a2 = dp4a_us(vb.y, w0.w, a2);
    a2 = dp4a_us(vb.z, kv4, a2);

    int a3 = dp4a_us(va.w, w0.x, MAGIC_I);
    a3 = dp4a_us(vb.x, w0.y, a3);
    a3 = dp4a_us(vb.y, w0.z, a3);
    a3 = dp4a_us(vb.z, w0.w, a3);
    a3 = dp4a_us(vb.w, kv4, a3);

    // f32x2 part: row ho+4. Pair (f0,f1) uses Xp[j], pair (f2,f3) Xp[j+2].
    // All intermediates exact integers offset by 12582912 (< 2^24).
    u64 f01 = pack2(__int_as_float(a0), __int_as_float(a1));
    u64 f23 = pack2(__int_as_float(a2), __int_as_float(a3));

    f01 = fma2(Xp[0], wp0, f01);
    f23 = fma2(Xp[2], wp0, f23);
    f01 = fma2(Xp[1], wp1, f01);
    f23 = fma2(Xp[3], wp1, f23);
    f01 = fma2(Xp[2], wp2, f01);
    f23 = fma2(Xp[4], wp2, f23);
    f01 = fma2(Xp[3], wp3, f01);
    f23 = fma2(Xp[5], wp3, f23);
    f01 = fma2(Xp[4], wp4, f01);
    f23 = fma2(Xp[6], wp4, f23);

    f01 = add2(f01, NMAGIC2);
    f23 = add2(f23, NMAGIC2);

    __stcs((double2*)pb, make_double2(__longlong_as_double((long long)f01),
                                      __longlong_as_double((long long)f23)));
}

// -------------------------------------------------------------------------
// Main conv kernel (R15 configuration: no forced occupancy, no spills).
// grid = B*HO*2 (1760). block = 256 threads = 8 warps = 8 channels.
// lane = wo-group; 2 passes cover 55 groups. ff advances by 2 with both
// weight sets loaded up front (LDS latency hidden behind 66 math ops).
// Weight tables per (c,f): W0 = packed rows0-3 cols0-3,
// WDab/WDcd = row-4 weights pre-DUPLICATED f32x2 pairs (wp0..wp3),
// Wmix = (kv4 in low 32 bits, wp4) -- one LDS.128 serves both.
// -------------------------------------------------------------------------
__global__ __launch_bounds__(256, 4) void conv_main_kernel(
    const float* __restrict__ kern, float* __restrict__ out)
{
    __shared__ __align__(16) unsigned Vsm[8][WW];     // 7168 B
    __shared__ unsigned R4sm[8][WG];                  // 1792 B
    __shared__ __align__(16) uint4 W0sm[256];         // 4096 B
    __shared__ __align__(16) ulonglong2 WDab[256];    // 4096 B (wp0, wp1)
    __shared__ __align__(16) ulonglong2 WDcd[256];    // 4096 B (wp2, wp3)
    __shared__ __align__(16) ulonglong2 Wmix[256];    // 4096 B (kv4, wp4)  25344 total

    int bid = blockIdx.x;
    int chalf = bid & 1;
    int t = bid >> 1;
    int ho = t % HO;
    int b = t / HO;
    int tid = threadIdx.x;
    int wid = tid >> 5;              // local channel 0..7
    int lane = tid & 31;
    int cg = chalf * 8 + wid;        // global channel

    // ---- Pack weights: thread = (local c, f) = (wid, lane) ----
    {
        int kk[25];
#pragma unroll
        for (int tt = 0; tt < 25; tt++)
            kk[tt] = (int)kern[tt * (CC * FF) + cg * FF + lane];
        unsigned Kv[5];
#pragma unroll
        for (int j = 0; j < 5; j++)
            Kv[j] = ((unsigned)(kk[j] & 0xFF))
                  | ((unsigned)(kk[5 + j] & 0xFF) << 8)
                  | ((unsigned)(kk[10 + j] & 0xFF) << 16)
                  | ((unsigned)(kk[15 + j] & 0xFF) << 24);
        W0sm[tid] = make_uint4(Kv[0], Kv[1], Kv[2], Kv[3]);
        unsigned d0 = __float_as_uint((float)kk[20]);
        unsigned d1 = __float_as_uint((float)kk[21]);
        unsigned d2 = __float_as_uint((float)kk[22]);
        unsigned d3 = __float_as_uint((float)kk[23]);
        unsigned d4 = __float_as_uint((float)kk[24]);
        WDab[tid] = make_ulonglong2(d0 | ((u64)d0 << 32), d1 | ((u64)d1 << 32));
        WDcd[tid] = make_ulonglong2(d2 | ((u64)d2 << 32), d3 | ((u64)d3 << 32));
        Wmix[tid] = make_ulonglong2((u64)Kv[4], d4 | ((u64)d4 << 32));
    }

    // ---- Stage 5 planar rows for our 8 channels; 8-PRMT vertical transpose ----
    const unsigned* P = (const unsigned*)g_planar;
    for (int l = tid; l < 8 * WG; l += 256) {
        int cc = l / WG, g = l % WG;
        const unsigned* base =
            P + ((size_t)(b * CC + chalf * 8 + cc) * HH + ho) * WG + g;
        unsigned r0 = base[0 * WG];
        unsigned r1 = base[1 * WG];
        unsigned r2 = base[2 * WG];
        unsigned r3 = base[3 * WG];
        unsigned r4 = base[4 * WG];
        unsigned t0 = __byte_perm(r0, r1, 0x5140);
        unsigned t1 = __byte_perm(r0, r1, 0x7362);
        unsigned t2 = __byte_perm(r2, r3, 0x5140);
        unsigned t3 = __byte_perm(r2, r3, 0x7362);
        uint4 v;
        v.x = __byte_perm(t0, t2, 0x5410);
        v.y = __byte_perm(t0, t2, 0x7632);
        v.z = __byte_perm(t1, t3, 0x5410);
        v.w = __byte_perm(t1, t3, 0x7632);
        *(uint4*)&Vsm[cc][4 * g] = v;
        R4sm[cc][g] = r4;
    }
    __syncthreads();

    const unsigned* Vrow = &Vsm[wid][0];
    const unsigned* R4 = &R4sm[wid][0];
    float* rowbase = out + ((size_t)(b * HO + ho) * CC + cg) * FF * WO;
    const int pbase = wid * 32;

#pragma unroll 1
    for (int pass = 0; pass < 2; pass++) {
        int g = lane + pass * 32;
        bool act = (g < 55);                 // 55 float4 groups cover WO=220
        uint4 va, vb;
        u64 Xp[7];                           // row ho+4 float pairs (X[j],X[j+1])
        if (act) {
            va = *(const uint4*)(Vrow + 4 * g);       // cols 4g..4g+3
            vb = *(const uint4*)(Vrow + 4 * g + 4);   // cols 4g+4..4g+7
            unsigned ra = R4[g];
            unsigned rb = R4[g + 1];
            float X4[8];
#pragma unroll
            for (int s = 0; s < 4; s++) {
                X4[s] = byte2f(ra, s);
                X4[4 + s] = byte2f(rb, s);
            }
#pragma unroll
            for (int j = 0; j < 7; j++)
                Xp[j] = pack2(X4[j], X4[j + 1]);
        }
        float* pb = rowbase + 4 * g;

#pragma unroll 2
        for (int ff = 0; ff < FF; ff += 2) {
            // Load BOTH iterations' weights first (4 LDS.128 each), then run
            // independent dp4a/FFMA2 chains -> LDS latency fully covered.
            uint4 w0a = W0sm[pbase + ff];
            ulonglong2 dab_a = WDab[pbase + ff];
            ulonglong2 dcd_a = WDcd[pbase + ff];
            ulonglong2 mx_a = Wmix[pbase + ff];
            uint4 w0b = W0sm[pbase + ff + 1];
            ulonglong2 dab_b = WDab[pbase + ff + 1];
            ulonglong2 dcd_b = WDcd[pbase + ff + 1];
            ulonglong2 mx_b = Wmix[pbase + ff + 1];

            if (act) {
                conv_group4(va, vb, Xp, w0a, (unsigned)mx_a.x,
                            dab_a.x, dab_a.y, dcd_a.x, dcd_a.y, mx_a.y,
                            pb + ff * WO);
                conv_group4(va, vb, Xp, w0b, (unsigned)mx_b.x,
                            dab_b.x, dab_b.y, dcd_b.x, dcd_b.y, mx_b.y,
                            pb + (ff + 1) * WO);
            }
        }
    }
}

// -------------------------------------------------------------------------
// kernel_launch: prepass + main conv. Graph-capturable: 2 launches, no sync,
// no allocation (scratch is a static __device__ array).
// -------------------------------------------------------------------------
extern "C" void kernel_launch(void* const* d_in, const int* in_sizes, int n_in,
                              void* d_out, int out_size) {
    const float* inputs = (const float*)d_in[0];  // [4,224,224,16] f32
    const float* kernel = (const float*)d_in[1];  // [5,5,16,32]    f32
    float* out = (float*)d_out;                   // [4,220,16,32,220] f32

    prepass_kernel<<<BB * HH / 2, 512>>>(inputs);
    conv_main_kernel<<<BB * HO * 2, 256>>>(kernel, out);
}